// round 16
// baseline (speedup 1.0000x reference)
#include <cuda_runtime.h>

// SSIM loss — (s,d)=(x+y,x-y) transform, two packed f32x2 rings, and an
// 11-row double-half staging ring with DEFERRED stores: the STS at iteration
// u writes the row loaded two iterations earlier, decoupling DRAM load
// latency from the consumer. 2 barriers per 11 rows. sm_103a packed math.
// 16x3x512x512 fp32 pred/target -> scalar 1 - mean(ssim_map).

#define IMG   512
#define PLANES 48
#define KW    11
#define KR    5
#define TW    128
#define TH    64
#define NRB   7                  // 7*11 = 77 rows streamed >= TH+10
#define NROWS 77
#define SW    (TW + 2*KR)        // 138
#define NTHREADS 128
#define GRIDX (IMG/TW)           // 4
#define GRIDY (IMG/TH)           // 8
#define NBLK  (GRIDX*GRIDY*PLANES)  // 1536
#define NPIXD ((double)PLANES * IMG * IMG)

typedef unsigned long long u64;

__device__ double       g_sum;
__device__ unsigned int g_cnt;

__device__ __forceinline__ u64 pk2(float x, float y) {
    u64 r; asm("mov.b64 %0, {%1, %2};" : "=l"(r) : "f"(x), "f"(y)); return r;
}
__device__ __forceinline__ void upk2(u64 v, float& x, float& y) {
    asm("mov.b64 {%0, %1}, %2;" : "=f"(x), "=f"(y) : "l"(v));
}
__device__ __forceinline__ u64 fma2(u64 a, u64 b, u64 c) {
    u64 d; asm("fma.rn.f32x2 %0, %1, %2, %3;" : "=l"(d) : "l"(a), "l"(b), "l"(c));
    return d;
}
__device__ __forceinline__ u64 mul2(u64 a, u64 b) {
    u64 d; asm("mul.rn.f32x2 %0, %1, %2;" : "=l"(d) : "l"(a), "l"(b));
    return d;
}

__global__ __launch_bounds__(NTHREADS, 5)
void ssim_kernel(const float* __restrict__ pred,
                 const float* __restrict__ targ,
                 float* __restrict__ out)
{
    constexpr float W[KW] = {
        0.00102838f, 0.00759876f, 0.03600077f, 0.10936069f, 0.21300554f,
        0.26601173f,
        0.21300554f, 0.10936069f, 0.03600077f, 0.00759876f, 0.00102838f
    };
    constexpr float TC1 = 0.0002f;   // 2 * 0.01^2  (0.5-factors folded out)
    constexpr float TC2 = 0.0018f;   // 2 * 0.03^2

    __shared__ float2 stg[2][KW][SW];   // two 11-row halves of (s,d) rows
    __shared__ float  wsum[4];

    const int t  = threadIdx.x;
    const int x0 = blockIdx.x * TW;
    const int y0 = blockIdx.y * TH;
    const float* __restrict__ xin = pred + (size_t)blockIdx.z * IMG * IMG;
    const float* __restrict__ yin = targ + (size_t)blockIdx.z * IMG * IMG;

    const int  gx0  = x0 - KR + t;
    const int  gx1  = gx0 + TW;
    const bool tail = (t < SW - TW);

    // PREDICATED row load (no branches -> LDGs issue early); rows >= NROWS
    // load as zero (never consumed). Returns (s,d) = (x+y, x-y).
    auto ldrow = [&](int r, float& s0, float& d0, float& s1, float& d1) {
        const int  gy  = y0 - KR + r;
        const bool rok = (r < NROWS) && (gy >= 0) && (gy < IMG);
        const bool ok0 = rok && (gx0 >= 0) && (gx0 < IMG);
        const bool ok1 = rok && tail && (gx1 < IMG);
        const long b = (long)gy * IMG;
        const float ax0 = ok0 ? xin[b + gx0] : 0.0f;
        const float ay0 = ok0 ? yin[b + gx0] : 0.0f;
        const float ax1 = ok1 ? xin[b + gx1] : 0.0f;
        const float ay1 = ok1 ? yin[b + gx1] : 0.0f;
        s0 = ax0 + ay0;  d0 = ax0 - ay0;
        s1 = ax1 + ay1;  d1 = ax1 - ay1;
    };

    // 6 distinct packed weights (Gaussian symmetry)
    u64 WW[6];
    #pragma unroll
    for (int k = 0; k < 6; ++k) WW[k] = pk2(W[k], W[k]);
    const u64 NEG1 = pk2(-1.0f, -1.0f);
    const u64 Z64  = 0ull;

    // ring accumulators: packed (mu_s, mu_d) and (E[s^2], E[d^2])
    u64 aMU[11], aSQ[11];
    #pragma unroll
    for (int s = 0; s < 11; ++s) { aMU[s] = Z64; aSQ[s] = Z64; }

    float tsum = 0.0f;

    // prefetch queue, 2 deep, parity-indexed (literal): holds (s0,d0,s1,d1)
    float pf[2][4];

    // ---- prologue: rows 0..8 staged directly; rows 9,10 into the queue ----
    #pragma unroll
    for (int r = 0; r < 9; ++r) {
        float s0, d0, s1, d1;
        ldrow(r, s0, d0, s1, d1);
        stg[0][r][t] = make_float2(s0, d0);
        if (tail) stg[0][r][TW + t] = make_float2(s1, d1);
    }
    ldrow(9,  pf[0][0], pf[0][1], pf[0][2], pf[0][3]);
    ldrow(10, pf[1][0], pf[1][1], pf[1][2], pf[1][3]);
    __syncthreads();

    for (int jb = 0; jb < NRB; ++jb) {
        float2 (*cur)[SW] = stg[jb & 1];          // uniform per block
        float2 (*nxt)[SW] = stg[(jb + 1) & 1];

        #pragma unroll
        for (int u = 0; u < 11; ++u) {
            const int j = jb * 11 + u;

            // ---- deferred STS: pf[u&1] holds row j+9 (loaded 2 iters ago);
            // destination slot is literal per unrolled u. Data is ready ->
            // no scoreboard wait here.
            {
                float2 (*dst)[SW] = (u < 2) ? cur : nxt;
                const int slot = (u < 2) ? (u + 9) : (u - 2);   // literal
                dst[slot][t] = make_float2(pf[u & 1][0], pf[u & 1][1]);
                if (tail) dst[slot][TW + t] = make_float2(pf[u & 1][2], pf[u & 1][3]);
            }
            // refill the queue: issue LDG for row j+11 (consumed at iter j+2)
            ldrow(j + 11, pf[u & 1][0], pf[u & 1][1], pf[u & 1][2], pf[u & 1][3]);

            // ---- horizontal blur from cur[u] (literal offset) ----
            const u64* s = (const u64*)cur[u];
            u64 hmu = Z64, hsq = Z64;
            #pragma unroll
            for (int k = 0; k < KW; ++k) {
                const int kw = (k < 6) ? k : 10 - k;    // literal
                const u64 p  = s[t + k];                // (s, d) LDS.64
                const u64 pp = mul2(p, p);              // (s^2, d^2)
                hmu = fma2(WW[kw], p,  hmu);
                hsq = fma2(WW[kw], pp, hsq);
            }

            // ---- vertical ring update: 2 packed ops per tap ----
            #pragma unroll
            for (int p = 0; p < KW; ++p) {
                const int ss = (u - p + 11) % 11;       // literal
                const int pw = (p < 6) ? p : 10 - p;    // literal
                aMU[ss] = fma2(WW[pw], hmu, aMU[ss]);
                aSQ[ss] = fma2(WW[pw], hsq, aSQ[ss]);
            }

            // ---- finalize output row o = j-10, reset slot ----
            {
                const int so = (u + 1) % 11;
                const int o  = j - (KW - 1);
                if (o >= 0 && o < TH) {
                    const u64 mu  = aMU[so];
                    const u64 mu2 = mul2(mu, mu);             // (mus^2, mud^2)
                    const u64 sg  = fma2(mu2, NEG1, aSQ[so]); // (sig_s, sig_d)
                    float g0, g1, v0, v1;
                    upk2(mu2, g0, g1);
                    upk2(sg,  v0, v1);
                    const float num = ((g0 - g1) + TC1) * ((v0 - v1) + TC2);
                    const float den = ((g0 + g1) + TC1) * ((v0 + v1) + TC2);
                    tsum += __fdividef(num, den);
                }
                aMU[so] = Z64; aSQ[so] = Z64;
            }

            // ---- barriers: mid-block (publishes cur[9],cur[10] before their
            // reads at u=9,10) and end-of-block (publishes nxt[0..8], retires
            // cur for reuse two blocks later).
            if (u == 1 || u == 10) __syncthreads();
        }
    }

    // ---- reduction: warp -> block -> global ----
    #pragma unroll
    for (int off = 16; off > 0; off >>= 1)
        tsum += __shfl_down_sync(0xffffffffu, tsum, off);
    if ((t & 31) == 0) wsum[t >> 5] = tsum;
    __syncthreads();

    if (t == 0) {
        const double bs = (double)wsum[0] + (double)wsum[1]
                        + (double)wsum[2] + (double)wsum[3];
        atomicAdd(&g_sum, bs);
        __threadfence();
        const unsigned r = atomicAdd(&g_cnt, 1u);
        if (r == NBLK - 1u) {
            const double sall = g_sum;
            out[0] = (float)(1.0 - sall / NPIXD);
            g_sum = 0.0;
            __threadfence();
            g_cnt = 0u;
        }
    }
}

extern "C" void kernel_launch(void* const* d_in, const int* in_sizes, int n_in,
                              void* d_out, int out_size)
{
    const float* pred = (const float*)d_in[0];
    const float* targ = (const float*)d_in[1];
    float* out = (float*)d_out;

    dim3 grid(GRIDX, GRIDY, PLANES);   // 4 x 8 x 48 = 1536 blocks
    ssim_kernel<<<grid, NTHREADS>>>(pred, targ, out);
}